// round 5
// baseline (speedup 1.0000x reference)
#include <cuda_runtime.h>
#include <cstdint>

#define TOKS 8192
#define EDIM 768
#define FDIM 3072
#define SEQ  1024
#define NH   12
#define HD   64
#define NLAYER 6

#define EE (EDIM * EDIM)
#define EF (EDIM * FDIM)
#define WT_PER_LAYER (4 * EE + 2 * EF)

// ---------------- scratch (device globals; no allocation) ----------------
__device__ float g_x[TOKS * EDIM];
__device__ float g_q[TOKS * EDIM];
__device__ float g_k[TOKS * EDIM];
__device__ float g_v[TOKS * EDIM];   // holds V^T: [b][h][hd][seq]
__device__ float g_att[TOKS * EDIM];
__device__ float g_t[TOKS * EDIM];
__device__ float g_ffn[TOKS * FDIM];
__device__ float g_pool[8 * EDIM];
__device__ float g_wt[(long)NLAYER * WT_PER_LAYER];  // transposed + RNA-rounded weights

// ---------------- helpers ----------------
__device__ __forceinline__ uint32_t f2tf32(float x) {
    uint32_t r;
    asm("cvt.rna.tf32.f32 %0, %1;" : "=r"(r) : "f"(x));
    return r;
}
__device__ __forceinline__ float rna_f(float x) { return __uint_as_float(f2tf32(x)); }

__device__ __forceinline__ void mma8(float* c, uint32_t a0, uint32_t a1, uint32_t a2, uint32_t a3,
                                     uint32_t b0, uint32_t b1) {
    asm volatile(
        "mma.sync.aligned.m16n8k8.row.col.f32.tf32.tf32.f32 "
        "{%0,%1,%2,%3}, {%4,%5,%6,%7}, {%8,%9}, {%0,%1,%2,%3};"
        : "+f"(c[0]), "+f"(c[1]), "+f"(c[2]), "+f"(c[3])
        : "r"(a0), "r"(a1), "r"(a2), "r"(a3), "r"(b0), "r"(b1));
}

__device__ __forceinline__ void ldsm4(uint32_t* r, uint32_t a) {
    asm volatile("ldmatrix.sync.aligned.m8n8.x4.shared.b16 {%0,%1,%2,%3}, [%4];"
                 : "=r"(r[0]), "=r"(r[1]), "=r"(r[2]), "=r"(r[3]) : "r"(a));
}

__device__ __forceinline__ void cp16(uint32_t saddr, const void* gaddr) {
    asm volatile("cp.async.cg.shared.global [%0], [%1], 16;" ::"r"(saddr), "l"(gaddr));
}
__device__ __forceinline__ void cp_commit() { asm volatile("cp.async.commit_group;"); }

__device__ __forceinline__ uint32_t smem_u32(const void* p) {
    uint32_t a;
    asm("{ .reg .u64 t; cvta.to.shared.u64 t, %1; cvt.u32.u64 %0, t; }" : "=r"(a) : "l"(p));
    return a;
}

// ---------------- batched weight transpose + RNA round ----------------
// dst[N][K] = rna(src[K][N]^T), one layer per blockIdx.z
__global__ void transpose_all(const float* __restrict__ src, float* __restrict__ dst,
                              int K, int N, long sstride, long dstride) {
    int lz = blockIdx.z;
    src += (long)lz * sstride;
    dst += (long)lz * dstride;
    __shared__ float tl[32][33];
    int n0 = blockIdx.x * 32, k0 = blockIdx.y * 32;
    int tx = threadIdx.x, ty = threadIdx.y;
#pragma unroll
    for (int j = 0; j < 32; j += 8) tl[ty + j][tx] = src[(long)(k0 + ty + j) * N + n0 + tx];
    __syncthreads();
#pragma unroll
    for (int j = 0; j < 32; j += 8)
        dst[(long)(n0 + ty + j) * K + k0 + tx] = rna_f(tl[tx][ty + j]);
}

// ---------------- embedding + positional encoding (RNA-rounded output) ----------------
__global__ void embed_kernel(const int* __restrict__ ids, const float* __restrict__ emb,
                             const float* __restrict__ pe, float* __restrict__ x) {
    long idx = (long)blockIdx.x * blockDim.x + threadIdx.x;
    if (idx >= (long)TOKS * EDIM) return;
    int tok = (int)(idx / EDIM);
    int e = (int)(idx - (long)tok * EDIM);
    int s = tok & (SEQ - 1);
    x[idx] = rna_f(emb[(long)ids[tok] * EDIM + e] + pe[s * EDIM + e]);
}

// ---------------- TF32 mma GEMM: block 128x256, warp tile 64x64, 3-stage cp.async ----
// C[M,N] = A[M,K] @ Wt[N,K]^T + bias.  256 thr = 8 warps (2x4).
// modes: 0 plain, 1 relu+rna, 2 rna, 3 rna + V^T scatter ([b][h][hd][seq])
struct Trip {
    const float* W;   // [N][K] transposed, pre-rounded
    const float* b;
    float* C;
    int mode;
};

#define GAS 18432              // A stage bytes: 128*144
#define GBS 36864              // B stage bytes: 256*144
#define GSTAGE (GAS + GBS)     // 55296
#define GEMM_SMEM (3 * GSTAGE)

__global__ __launch_bounds__(256, 1) void gemm_lds(const float* __restrict__ A,
                                                   Trip t0, Trip t1, Trip t2,
                                                   int N, int K) {
    extern __shared__ __align__(128) char smc[];
    uint32_t sb = smem_u32(smc);
    int t = threadIdx.x, l = t & 31, warp = t >> 5;
    int wm = warp >> 2, wn = warp & 3;
    int g = l >> 2, tg = l & 3;

    int z = blockIdx.z;
    Trip tr = (z == 0) ? t0 : (z == 1) ? t1 : t2;
    long bm = blockIdx.y, bn = blockIdx.x;
    const float* Ab = A + bm * 128 * (long)K;
    const float* Bb = tr.W + bn * 256 * (long)K;

    int ra = t >> 3, seg = t & 7;

    // ldmatrix per-thread offsets (bytes), relative to stage base
    uint32_t aOff[4], bOff[4];
#pragma unroll
    for (int mf = 0; mf < 4; mf++)
        aOff[mf] = (uint32_t)((wm * 64 + mf * 16 + (l & 7) + ((l >> 3) & 1) * 8) * 144 +
                              (l >> 4) * 16);
#pragma unroll
    for (int j = 0; j < 4; j++)
        bOff[j] = (uint32_t)(GAS +
                             (wn * 64 + (2 * j + (l >> 4)) * 8 + (l & 7)) * 144 +
                             ((l >> 3) & 1) * 16);

    float acc[4][8][4];
#pragma unroll
    for (int i = 0; i < 4; i++)
#pragma unroll
        for (int j = 0; j < 8; j++)
#pragma unroll
            for (int q = 0; q < 4; q++) acc[i][j][q] = 0.f;

    int niter = K >> 5;

    // prologue: chunks 0, 1
#pragma unroll
    for (int st = 0; st < 2; st++) {
        uint32_t sA = sb + st * GSTAGE, sB = sA + GAS;
        int k0 = st * 32;
#pragma unroll
        for (int p = 0; p < 4; p++) {
            int r = ra + p * 32;
            cp16(sA + (uint32_t)(r * 144 + seg * 16), Ab + (long)r * K + k0 + seg * 4);
        }
#pragma unroll
        for (int p = 0; p < 8; p++) {
            int r = ra + p * 32;
            cp16(sB + (uint32_t)(r * 144 + seg * 16), Bb + (long)r * K + k0 + seg * 4);
        }
        cp_commit();
    }

    int s = 0;
    for (int it = 0; it < niter; it++) {
        asm volatile("cp.async.wait_group 1;");
        __syncthreads();

        int jn = it + 2;
        if (jn < niter) {
            int s2 = jn % 3;
            uint32_t sA2 = sb + s2 * GSTAGE, sB2 = sA2 + GAS;
            int k0 = jn * 32;
#pragma unroll
            for (int p = 0; p < 4; p++) {
                int r = ra + p * 32;
                cp16(sA2 + (uint32_t)(r * 144 + seg * 16), Ab + (long)r * K + k0 + seg * 4);
            }
#pragma unroll
            for (int p = 0; p < 8; p++) {
                int r = ra + p * 32;
                cp16(sB2 + (uint32_t)(r * 144 + seg * 16), Bb + (long)r * K + k0 + seg * 4);
            }
        }
        cp_commit();

        uint32_t sA = sb + s * GSTAGE;
#pragma unroll
        for (int kk = 0; kk < 4; kk++) {
            uint32_t af[4][4], bf[8][2];
#pragma unroll
            for (int mf = 0; mf < 4; mf++) ldsm4(af[mf], sA + aOff[mf] + kk * 32);
#pragma unroll
            for (int j = 0; j < 4; j++) ldsm4(&bf[2 * j][0], sA + bOff[j] + kk * 32);
#pragma unroll
            for (int mf = 0; mf < 4; mf++)
#pragma unroll
                for (int nf = 0; nf < 8; nf++)
                    mma8(acc[mf][nf], af[mf][0], af[mf][1], af[mf][2], af[mf][3],
                         bf[nf][0], bf[nf][1]);
        }
        s = (s == 2) ? 0 : s + 1;
    }

    // epilogue
    int mode = tr.mode;
    const float* bias = tr.b;
    float* C = tr.C;
#pragma unroll
    for (int mf = 0; mf < 4; mf++) {
        int r0 = (int)bm * 128 + wm * 64 + mf * 16 + g;
#pragma unroll
        for (int nf = 0; nf < 8; nf++) {
            int c0 = (int)bn * 256 + wn * 64 + nf * 8 + 2 * tg;
            float bb0 = bias[c0], bb1 = bias[c0 + 1];
            float v0 = acc[mf][nf][0] + bb0;
            float v1 = acc[mf][nf][1] + bb1;
            float v2 = acc[mf][nf][2] + bb0;
            float v3 = acc[mf][nf][3] + bb1;
            if (mode == 1) {
                v0 = rna_f(fmaxf(v0, 0.f)); v1 = rna_f(fmaxf(v1, 0.f));
                v2 = rna_f(fmaxf(v2, 0.f)); v3 = rna_f(fmaxf(v3, 0.f));
            } else if (mode >= 2) {
                v0 = rna_f(v0); v1 = rna_f(v1); v2 = rna_f(v2); v3 = rna_f(v3);
            }
            if (mode == 3) {
                int b_ = r0 >> 10, sp = r0 & 1023;
                int h0 = c0 >> 6, d0 = c0 & 63;
                long vb = ((long)(b_ * NH + h0) * HD + d0) * SEQ + sp;
                C[vb] = v0;
                C[vb + SEQ] = v1;
                C[vb + 8] = v2;
                C[vb + SEQ + 8] = v3;
            } else {
                *(float2*)&C[(long)r0 * N + c0] = make_float2(v0, v1);
                *(float2*)&C[(long)(r0 + 8) * N + c0] = make_float2(v2, v3);
            }
        }
    }
}

// ---------------- fused flash attention ----------------
// block 128 thr (4 warps), q-tile 64, K/V key-tiles of 64 double-buffered via cp.async.
// smem layout (bytes): Q[64][68] @0, P[64][68] @17408, mask[1024] @34816,
// stages @38912 + s*34816 : K[64][68] then V^T[64][68]
#define ATT_SMEM 108544

__global__ __launch_bounds__(128) void attn_kernel(const float* __restrict__ Q,
                                                   const float* __restrict__ Kp,
                                                   const float* __restrict__ Vt,
                                                   const int* __restrict__ mask,
                                                   float* __restrict__ O) {
    extern __shared__ __align__(128) char smc[];
    uint32_t sb = smem_u32(smc);
    float* mAdd = (float*)(smc + 34816);

    int t = threadIdx.x, l = t & 31, warp = t >> 5;
    int g = l >> 2, tg = l & 3;
    int b = blockIdx.z, h = blockIdx.y, qt = blockIdx.x;
    int rq = warp * 16;

    const float* Qb = Q + ((long)(b * SEQ + qt * 64)) * EDIM + h * HD;
    const float* Kb = Kp + ((long)(b * SEQ)) * EDIM + h * HD;
    const float* Vb = Vt + ((long)(b * NH + h) * HD) * SEQ;

    uint32_t aQoff = (uint32_t)((rq + (l & 7) + ((l >> 3) & 1) * 8) * 272 + (l >> 4) * 16);
    uint32_t bOff[4];
#pragma unroll
    for (int j = 0; j < 4; j++)
        bOff[j] = (uint32_t)(((2 * j + (l >> 4)) * 8 + (l & 7)) * 272 + ((l >> 3) & 1) * 16);

    {
        int r = t >> 1;
        int s0 = (t & 1) * 8;
#pragma unroll
        for (int j = 0; j < 8; j++)
            cp16(sb + (uint32_t)(r * 272 + (s0 + j) * 16), Qb + (long)r * EDIM + (s0 + j) * 4);
        cp_commit();
    }
    for (int i = t; i < SEQ; i += 128) mAdd[i] = mask[b * SEQ + i] ? 0.f : -1e30f;

#pragma unroll
    for (int st = 0; st < 2; st++) {
        uint32_t Kst = sb + 38912 + st * 34816, Vst = Kst + 17408;
        int r = t >> 1, s0 = (t & 1) * 8;
        const float* Ks = Kb + (long)(st * 64) * EDIM;
        const float* Vs = Vb + st * 64;
#pragma unroll
        for (int j = 0; j < 8; j++) {
            cp16(Kst + (uint32_t)(r * 272 + (s0 + j) * 16), Ks + (long)r * EDIM + (s0 + j) * 4);
            cp16(Vst + (uint32_t)(r * 272 + (s0 + j) * 16), Vs + (long)r * SEQ + (s0 + j) * 4);
        }
        cp_commit();
    }

    float m_[2] = {-INFINITY, -INFINITY};
    float l_[2] = {0.f, 0.f};
    float o[8][4];
#pragma unroll
    for (int nf = 0; nf < 8; nf++)
#pragma unroll
        for (int q = 0; q < 4; q++) o[nf][q] = 0.f;

    for (int kt = 0; kt < 16; kt++) {
        int s = kt & 1;
        uint32_t Kst = sb + 38912 + s * 34816, Vst = Kst + 17408;
        asm volatile("cp.async.wait_group 1;");
        __syncthreads();

        float sc[8][4];
#pragma unroll
        for (int nf = 0; nf < 8; nf++)
#pragma unroll
            for (int q = 0; q < 4; q++) sc[nf][q] = 0.f;
#pragma unroll
        for (int kk = 0; kk < 8; kk++) {
            uint32_t af[4], bf[8][2];
            ldsm4(af, sb + aQoff + kk * 32);
#pragma unroll
            for (int j = 0; j < 4; j++) ldsm4(&bf[2 * j][0], Kst + bOff[j] + kk * 32);
#pragma unroll
            for (int nf = 0; nf < 8; nf++)
                mma8(sc[nf], af[0], af[1], af[2], af[3], bf[nf][0], bf[nf][1]);
        }

        float rmax0 = -INFINITY, rmax1 = -INFINITY;
#pragma unroll
        for (int nf = 0; nf < 8; nf++) {
            int c0 = kt * 64 + nf * 8 + 2 * tg;
            float ma = mAdd[c0], mb = mAdd[c0 + 1];
            sc[nf][0] = sc[nf][0] * 0.125f + ma;
            sc[nf][1] = sc[nf][1] * 0.125f + mb;
            sc[nf][2] = sc[nf][2] * 0.125f + ma;
            sc[nf][3] = sc[nf][3] * 0.125f + mb;
            rmax0 = fmaxf(rmax0, fmaxf(sc[nf][0], sc[nf][1]));
            rmax1 = fmaxf(rmax1, fmaxf(sc[nf][2], sc[nf][3]));
        }
        rmax0 = fmaxf(rmax0, __shfl_xor_sync(0xffffffffu, rmax0, 1));
        rmax0 = fmaxf(rmax0, __shfl_xor_sync(0xffffffffu, rmax0, 2));
        rmax1 = fmaxf(rmax1, __shfl_xor_sync(0xffffffffu, rmax1, 1));
        rmax1 = fmaxf(rmax1, __shfl_xor_sync(0xffffffffu, rmax1, 2));
        float mn0 = fmaxf(m_[0], rmax0), mn1 = fmaxf(m_[1], rmax1);
        float cf0 = __expf(m_[0] - mn0), cf1 = __expf(m_[1] - mn1);
        float rs0 = 0.f, rs1 = 0.f;
#pragma unroll
        for (int nf = 0; nf < 8; nf++) {
            sc[nf][0] = __expf(sc[nf][0] - mn0);
            sc[nf][1] = __expf(sc[nf][1] - mn0);
            sc[nf][2] = __expf(sc[nf][2] - mn1);
            sc[nf][3] = __expf(sc[nf][3] - mn1);
            rs0 += sc[nf][0] + sc[nf][1];
            rs1 += sc[nf][2] + sc[nf][3];
        }
        rs0 += __shfl_xor_sync(0xffffffffu, rs0, 1);
        rs0 += __shfl_xor_sync(0xffffffffu, rs0, 2);
        rs1 += __shfl_xor_sync(0xffffffffu, rs1, 1);
        rs1 += __shfl_xor_sync(0xffffffffu, rs1, 2);
        l_[0] = l_[0] * cf0 + rs0;
        l_[1] = l_[1] * cf1 + rs1;
        m_[0] = mn0; m_[1] = mn1;
#pragma unroll
        for (int nf = 0; nf < 8; nf++) {
            o[nf][0] *= cf0; o[nf][1] *= cf0;
            o[nf][2] *= cf1; o[nf][3] *= cf1;
        }

#pragma unroll
        for (int nf = 0; nf < 8; nf++) {
            int pc = nf * 8 + 2 * tg;
            uint32_t a0 = sb + 17408 + (uint32_t)((rq + g) * 272 + pc * 4);
            uint32_t a1 = sb + 17408 + (uint32_t)((rq + 8 + g) * 272 + pc * 4);
            asm volatile("st.shared.v2.b32 [%0], {%1, %2};" ::"r"(a0),
                         "r"(f2tf32(sc[nf][0])), "r"(f2tf32(sc[nf][1])) : "memory");
            asm volatile("st.shared.v2.b32 [%0], {%1, %2};" ::"r"(a1),
                         "r"(f2tf32(sc[nf][2])), "r"(f2tf32(sc[nf][3])) : "memory");
        }
        __syncwarp();
#pragma unroll
        for (int kk = 0; kk < 8; kk++) {
            uint32_t af[4], bf[8][2];
            ldsm4(af, sb + 17408 + aQoff + kk * 32);
#pragma unroll
            for (int j = 0; j < 4; j++) ldsm4(&bf[2 * j][0], Vst + bOff[j] + kk * 32);
#pragma unroll
            for (int nf = 0; nf < 8; nf++)
                mma8(o[nf], af[0], af[1], af[2], af[3], bf[nf][0], bf[nf][1]);
        }
        __syncthreads();

        int jn = kt + 2;
        if (jn < 16) {
            int r = t >> 1, s0 = (t & 1) * 8;
            const float* Ks = Kb + (long)(jn * 64) * EDIM;
            const float* Vs = Vb + jn * 64;
#pragma unroll
            for (int j = 0; j < 8; j++) {
                cp16(Kst + (uint32_t)(r * 272 + (s0 + j) * 16), Ks + (long)r * EDIM + (s0 + j) * 4);
                cp16(Vst + (uint32_t)(r * 272 + (s0 + j) * 16), Vs + (long)r * SEQ + (s0 + j) * 4);
            }
        }
        cp_commit();
    }

    float il0 = 1.f / l_[0], il1 = 1.f / l_[1];
#pragma unroll
    for (int nf = 0; nf < 8; nf++) {
        long rowg = (long)(b * SEQ + qt * 64 + rq + g);
        int colg = h * HD + nf * 8 + 2 * tg;
        O[rowg * EDIM + colg] = rna_f(o[nf][0] * il0);
        O[rowg * EDIM + colg + 1] = rna_f(o[nf][1] * il0);
        O[(rowg + 8) * EDIM + colg] = rna_f(o[nf][2] * il1);
        O[(rowg + 8) * EDIM + colg + 1] = rna_f(o[nf][3] * il1);
    }
}

// ---------------- fused residual add + LayerNorm (RNA output) ----------------
__global__ __launch_bounds__(256) void ln_res_kernel(const float* __restrict__ x,
                                                     const float* __restrict__ y,
                                                     const float* __restrict__ gam,
                                                     const float* __restrict__ bet,
                                                     float* __restrict__ out) {
    int row = blockIdx.x, t = threadIdx.x;
    const float* xr = x + (long)row * EDIM;
    const float* yr = y + (long)row * EDIM;
    float v0 = xr[t] + yr[t];
    float v1 = xr[t + 256] + yr[t + 256];
    float v2 = xr[t + 512] + yr[t + 512];
    float s1 = v0 + v1 + v2;
    float s2 = v0 * v0 + v1 * v1 + v2 * v2;
    __shared__ float sh[2][8];
    __shared__ float stats[2];
    int lane = t & 31, w = t >> 5;
#pragma unroll
    for (int off = 16; off; off >>= 1) {
        s1 += __shfl_xor_sync(0xffffffffu, s1, off);
        s2 += __shfl_xor_sync(0xffffffffu, s2, off);
    }
    if (!lane) { sh[0][w] = s1; sh[1][w] = s2; }
    __syncthreads();
    if (t == 0) {
        float a = 0.f, bq = 0.f;
        for (int i = 0; i < 8; i++) { a += sh[0][i]; bq += sh[1][i]; }
        float mean = a * (1.f / EDIM);
        float var = bq * (1.f / EDIM) - mean * mean;
        stats[0] = mean;
        stats[1] = rsqrtf(var + 1e-5f);
    }
    __syncthreads();
    float mean = stats[0], rstd = stats[1];
    long base = (long)row * EDIM;
    out[base + t] = rna_f((v0 - mean) * rstd * gam[t] + bet[t]);
    out[base + t + 256] = rna_f((v1 - mean) * rstd * gam[t + 256] + bet[t + 256]);
    out[base + t + 512] = rna_f((v2 - mean) * rstd * gam[t + 512] + bet[t + 512]);
}

// ---------------- mean pool ----------------
__global__ void pool_kernel(const float* __restrict__ x, float* __restrict__ p) {
    int idx = blockIdx.x * blockDim.x + threadIdx.x;
    if (idx >= 8 * EDIM) return;
    int b = idx / EDIM, e = idx % EDIM;
    const float* xb = x + (long)b * SEQ * EDIM + e;
    float s = 0.f;
    for (int si = 0; si < SEQ; si++) s += xb[(long)si * EDIM];
    p[idx] = s * (1.f / SEQ);
}

// ---------------- classifier ----------------
__global__ void cls_kernel(const float* __restrict__ p, const float* __restrict__ Wc,
                           const float* __restrict__ bc, float* __restrict__ out) {
    int w = threadIdx.x >> 5, lane = threadIdx.x & 31;
    int b = w >> 1, c = w & 1;
    float s = 0.f;
    for (int e = lane; e < EDIM; e += 32) s += p[b * EDIM + e] * Wc[e * 2 + c];
#pragma unroll
    for (int off = 16; off; off >>= 1) s += __shfl_xor_sync(0xffffffffu, s, off);
    if (!lane) out[b * 2 + c] = s + bc[c];
}

// ---------------- launch ----------------
extern "C" void kernel_launch(void* const* d_in, const int* in_sizes, int n_in,
                              void* d_out, int out_size) {
    (void)in_sizes; (void)n_in; (void)out_size;
    const int* ids = (const int*)d_in[0];
    const int* amask = (const int*)d_in[1];
    const float* emb = (const float*)d_in[2];
    const float* pe = (const float*)d_in[3];
    const float* Wq = (const float*)d_in[4];
    const float* bq = (const float*)d_in[5];
    const float* Wk = (const float*)d_in[6];
    const float* bk = (const float*)d_in[7];
    const float* Wv = (const float*)d_in[8];
    const float* bv = (const float*)d_in[9];
    const float* Wo = (const float*)d_in[10];
    const float* bo = (const float*)d_in[11];
    const float* l1g = (const float*)d_in[12];
    const float* l1b = (const float*)d_in[13];
    const float* W1 = (const float*)d_in[14];
    const float* b1 = (const float*)d_in[15];
    const float* W2 = (const float*)d_in[16];
    const float* b2 = (const float*)d_in[17];
    const float* l2g = (const float*)d_in[18];
    const float* l2b = (const float*)d_in[19];
    const float* Wc = (const float*)d_in[20];
    const float* bc = (const float*)d_in[21];
    float* out = (float*)d_out;

    float *x, *q, *k, *v, *att, *tmp, *ffn, *pl, *wt;
    cudaGetSymbolAddress((void**)&x, g_x);
    cudaGetSymbolAddress((void**)&q, g_q);
    cudaGetSymbolAddress((void**)&k, g_k);
    cudaGetSymbolAddress((void**)&v, g_v);
    cudaGetSymbolAddress((void**)&att, g_att);
    cudaGetSymbolAddress((void**)&tmp, g_t);
    cudaGetSymbolAddress((void**)&ffn, g_ffn);
    cudaGetSymbolAddress((void**)&pl, g_pool);
    cudaGetSymbolAddress((void**)&wt, g_wt);

    cudaFuncSetAttribute(gemm_lds, cudaFuncAttributeMaxDynamicSharedMemorySize, GEMM_SMEM);
    cudaFuncSetAttribute(attn_kernel, cudaFuncAttributeMaxDynamicSharedMemorySize, ATT_SMEM);

    // one-time per launch: transpose + RNA-round all weights (batched over layers)
    dim3 tb(32, 8);
    transpose_all<<<dim3(EDIM / 32, EDIM / 32, NLAYER), tb>>>(Wq, wt + 0L * EE, EDIM, EDIM,
                                                             (long)EE, (long)WT_PER_LAYER);
    transpose_all<<<dim3(EDIM / 32, EDIM / 32, NLAYER), tb>>>(Wk, wt + 1L * EE, EDIM, EDIM,
                                                             (long)EE, (long)WT_PER_LAYER);
    transpose_all<<<dim3(EDIM / 32, EDIM / 32, NLAYER), tb>>>(Wv, wt + 2L * EE, EDIM, EDIM,
                                                             (long)EE, (long)WT_PER_LAYER);
    transpose_all<<<dim3(EDIM / 32, EDIM / 32, NLAYER), tb>>>(Wo, wt + 3L * EE, EDIM, EDIM,
                                                             (long)EE, (long)WT_PER_LAYER);
    transpose_all<<<dim3(FDIM / 32, EDIM / 32, NLAYER), tb>>>(W1, wt + 4L * EE, EDIM, FDIM,
                                                             (long)EF, (long)WT_PER_LAYER);
    transpose_all<<<dim3(EDIM / 32, FDIM / 32, NLAYER), tb>>>(W2, wt + 4L * EE + EF, FDIM, EDIM,
                                                             (long)EF, (long)WT_PER_LAYER);

    embed_kernel<<<(TOKS * EDIM + 255) / 256, 256>>>(ids, emb, pe, x);

    for (int l = 0; l < NLAYER; l++) {
        long boff = (long)l * EDIM;
        float* base = wt + (long)l * WT_PER_LAYER;
        Trip tq = {base + 0L * EE, bq + boff, q, 2};
        Trip tk = {base + 1L * EE, bk + boff, k, 2};
        Trip tv = {base + 2L * EE, bv + boff, v, 3};
        gemm_lds<<<dim3(3, 64, 3), 256, GEMM_SMEM>>>(x, tq, tk, tv, EDIM, EDIM);
        attn_kernel<<<dim3(16, 12, 8), 128, ATT_SMEM>>>(q, k, v, amask, att);
        Trip to = {base + 3L * EE, bo + boff, tmp, 0};
        gemm_lds<<<dim3(3, 64, 1), 256, GEMM_SMEM>>>(att, to, to, to, EDIM, EDIM);
        ln_res_kernel<<<TOKS, 256>>>(x, tmp, l1g + boff, l1b + boff, x);
        Trip t1 = {base + 4L * EE, b1 + (long)l * FDIM, ffn, 1};
        gemm_lds<<<dim3(12, 64, 1), 256, GEMM_SMEM>>>(x, t1, t1, t1, FDIM, EDIM);
        Trip t2 = {base + 4L * EE + EF, b2 + boff, tmp, 0};
        gemm_lds<<<dim3(3, 64, 1), 256, GEMM_SMEM>>>(ffn, t2, t2, t2, EDIM, FDIM);
        ln_res_kernel<<<TOKS, 256>>>(x, tmp, l2g + boff, l2b + boff, x);
    }

    pool_kernel<<<(8 * EDIM + 255) / 256, 256>>>(x, pl);
    cls_kernel<<<1, 512>>>(pl, Wc, bc, out);
}

// round 6
// speedup vs baseline: 1.2379x; 1.2379x over previous
#include <cuda_runtime.h>
#include <cstdint>

#define TOKS 8192
#define EDIM 768
#define FDIM 3072
#define SEQ  1024
#define NH   12
#define HD   64
#define NLAYER 6

#define EE (EDIM * EDIM)
#define EF (EDIM * FDIM)
#define WT_PER_LAYER (4 * EE + 2 * EF)

// ---------------- scratch (device globals; no allocation) ----------------
__device__ float g_x[TOKS * EDIM];
__device__ float g_q[TOKS * EDIM];
__device__ float g_k[TOKS * EDIM];
__device__ float g_v[TOKS * EDIM];   // holds V^T: [b][h][hd][seq]
__device__ float g_att[TOKS * EDIM];
__device__ float g_t[TOKS * EDIM];
__device__ float g_ffn[TOKS * FDIM];
__device__ float g_pool[8 * EDIM];
__device__ float g_wt[(long)NLAYER * WT_PER_LAYER];  // transposed + RNA-rounded weights

// ---------------- helpers ----------------
__device__ __forceinline__ uint32_t f2tf32(float x) {
    uint32_t r;
    asm("cvt.rna.tf32.f32 %0, %1;" : "=r"(r) : "f"(x));
    return r;
}
__device__ __forceinline__ float rna_f(float x) { return __uint_as_float(f2tf32(x)); }

__device__ __forceinline__ void mma8(float* c, uint32_t a0, uint32_t a1, uint32_t a2, uint32_t a3,
                                     uint32_t b0, uint32_t b1) {
    asm volatile(
        "mma.sync.aligned.m16n8k8.row.col.f32.tf32.tf32.f32 "
        "{%0,%1,%2,%3}, {%4,%5,%6,%7}, {%8,%9}, {%0,%1,%2,%3};"
        : "+f"(c[0]), "+f"(c[1]), "+f"(c[2]), "+f"(c[3])
        : "r"(a0), "r"(a1), "r"(a2), "r"(a3), "r"(b0), "r"(b1));
}

__device__ __forceinline__ void ldsm4(uint32_t* r, uint32_t a) {
    asm volatile("ldmatrix.sync.aligned.m8n8.x4.shared.b16 {%0,%1,%2,%3}, [%4];"
                 : "=r"(r[0]), "=r"(r[1]), "=r"(r[2]), "=r"(r[3]) : "r"(a));
}

__device__ __forceinline__ void cp16(uint32_t saddr, const void* gaddr) {
    asm volatile("cp.async.cg.shared.global [%0], [%1], 16;" ::"r"(saddr), "l"(gaddr));
}
__device__ __forceinline__ void cp_commit() { asm volatile("cp.async.commit_group;"); }

__device__ __forceinline__ uint32_t smem_u32(const void* p) {
    uint32_t a;
    asm("{ .reg .u64 t; cvta.to.shared.u64 t, %1; cvt.u32.u64 %0, t; }" : "=r"(a) : "l"(p));
    return a;
}

// ---------------- batched weight transpose + RNA round ----------------
// dst[N][K] = rna(src[K][N]^T), one layer per blockIdx.z
__global__ void transpose_all(const float* __restrict__ src, float* __restrict__ dst,
                              int K, int N, long sstride, long dstride) {
    int lz = blockIdx.z;
    src += (long)lz * sstride;
    dst += (long)lz * dstride;
    __shared__ float tl[32][33];
    int n0 = blockIdx.x * 32, k0 = blockIdx.y * 32;
    int tx = threadIdx.x, ty = threadIdx.y;
#pragma unroll
    for (int j = 0; j < 32; j += 8) tl[ty + j][tx] = src[(long)(k0 + ty + j) * N + n0 + tx];
    __syncthreads();
#pragma unroll
    for (int j = 0; j < 32; j += 8)
        dst[(long)(n0 + ty + j) * K + k0 + tx] = rna_f(tl[tx][ty + j]);
}

// ---------------- embedding + positional encoding (RNA-rounded output) ----------------
__global__ void embed_kernel(const int* __restrict__ ids, const float* __restrict__ emb,
                             const float* __restrict__ pe, float* __restrict__ x) {
    long idx = (long)blockIdx.x * blockDim.x + threadIdx.x;
    if (idx >= (long)TOKS * EDIM) return;
    int tok = (int)(idx / EDIM);
    int e = (int)(idx - (long)tok * EDIM);
    int s = tok & (SEQ - 1);
    x[idx] = rna_f(emb[(long)ids[tok] * EDIM + e] + pe[s * EDIM + e]);
}

// ---------------- TF32 mma GEMM, ldmatrix fragments, 3-stage cp.async -------------
// C[M,N] = A[M,K] @ Wt[N,K]^T + bias.  block 128x128, BK=32, 256 thr = 8 warps (2x4).
// modes: 0 plain, 1 relu+rna, 2 rna, 3 rna + V^T scatter ([b][h][hd][seq])
struct Trip {
    const float* W;   // [N][K] transposed, pre-rounded
    const float* b;
    float* C;
    int mode;
};

#define GSTAGE 36864  // A 18432 + B 18432
#define GEMM_SMEM (3 * GSTAGE)

__global__ __launch_bounds__(256, 2) void gemm_lds(const float* __restrict__ A,
                                                   Trip t0, Trip t1, Trip t2,
                                                   int N, int K) {
    extern __shared__ __align__(128) char smc[];
    uint32_t sb = smem_u32(smc);
    int t = threadIdx.x, l = t & 31, warp = t >> 5;
    int wm = warp >> 2, wn = warp & 3;
    int g = l >> 2, tg = l & 3;

    int z = blockIdx.z;
    Trip tr = (z == 0) ? t0 : (z == 1) ? t1 : t2;
    long bm = blockIdx.y, bn = blockIdx.x;
    const float* Ab = A + bm * 128 * (long)K;
    const float* Bb = tr.W + bn * 128 * (long)K;

    int ra = t >> 3, seg = t & 7;

    uint32_t aOff[4], bOff[2];
#pragma unroll
    for (int mf = 0; mf < 4; mf++)
        aOff[mf] = (uint32_t)((wm * 64 + mf * 16 + (l & 7) + ((l >> 3) & 1) * 8) * 144 +
                              (l >> 4) * 16);
#pragma unroll
    for (int j = 0; j < 2; j++)
        bOff[j] = (uint32_t)(18432 +
                             (wn * 32 + (2 * j + (l >> 4)) * 8 + (l & 7)) * 144 +
                             ((l >> 3) & 1) * 16);

    float acc[4][4][4];
#pragma unroll
    for (int i = 0; i < 4; i++)
#pragma unroll
        for (int j = 0; j < 4; j++)
#pragma unroll
            for (int q = 0; q < 4; q++) acc[i][j][q] = 0.f;

    int niter = K >> 5;

#pragma unroll
    for (int st = 0; st < 2; st++) {
        uint32_t sA = sb + st * GSTAGE, sB = sA + 18432;
        int k0 = st * 32;
#pragma unroll
        for (int p = 0; p < 4; p++) {
            int r = ra + p * 32;
            cp16(sA + (uint32_t)(r * 144 + seg * 16), Ab + (long)r * K + k0 + seg * 4);
            cp16(sB + (uint32_t)(r * 144 + seg * 16), Bb + (long)r * K + k0 + seg * 4);
        }
        cp_commit();
    }

    int s = 0;
    for (int it = 0; it < niter; it++) {
        asm volatile("cp.async.wait_group 1;");
        __syncthreads();

        int jn = it + 2;
        if (jn < niter) {
            int s2 = jn % 3;
            uint32_t sA2 = sb + s2 * GSTAGE, sB2 = sA2 + 18432;
            int k0 = jn * 32;
#pragma unroll
            for (int p = 0; p < 4; p++) {
                int r = ra + p * 32;
                cp16(sA2 + (uint32_t)(r * 144 + seg * 16), Ab + (long)r * K + k0 + seg * 4);
                cp16(sB2 + (uint32_t)(r * 144 + seg * 16), Bb + (long)r * K + k0 + seg * 4);
            }
        }
        cp_commit();

        uint32_t sA = sb + s * GSTAGE;
#pragma unroll
        for (int kk = 0; kk < 4; kk++) {
            uint32_t af[4][4], bf[4][2];
#pragma unroll
            for (int mf = 0; mf < 4; mf++) ldsm4(af[mf], sA + aOff[mf] + kk * 32);
#pragma unroll
            for (int j = 0; j < 2; j++) ldsm4(&bf[2 * j][0], sA + bOff[j] + kk * 32);
#pragma unroll
            for (int mf = 0; mf < 4; mf++)
#pragma unroll
                for (int nf = 0; nf < 4; nf++)
                    mma8(acc[mf][nf], af[mf][0], af[mf][1], af[mf][2], af[mf][3],
                         bf[nf][0], bf[nf][1]);
        }
        s = (s == 2) ? 0 : s + 1;
    }

    int mode = tr.mode;
    const float* bias = tr.b;
    float* C = tr.C;
#pragma unroll
    for (int mf = 0; mf < 4; mf++) {
        int r0 = (int)bm * 128 + wm * 64 + mf * 16 + g;
#pragma unroll
        for (int nf = 0; nf < 4; nf++) {
            int c0 = (int)bn * 128 + wn * 32 + nf * 8 + 2 * tg;
            float bb0 = bias[c0], bb1 = bias[c0 + 1];
            float v0 = acc[mf][nf][0] + bb0;
            float v1 = acc[mf][nf][1] + bb1;
            float v2 = acc[mf][nf][2] + bb0;
            float v3 = acc[mf][nf][3] + bb1;
            if (mode == 1) {
                v0 = rna_f(fmaxf(v0, 0.f)); v1 = rna_f(fmaxf(v1, 0.f));
                v2 = rna_f(fmaxf(v2, 0.f)); v3 = rna_f(fmaxf(v3, 0.f));
            } else if (mode >= 2) {
                v0 = rna_f(v0); v1 = rna_f(v1); v2 = rna_f(v2); v3 = rna_f(v3);
            }
            if (mode == 3) {
                int b_ = r0 >> 10, sp = r0 & 1023;
                int h0 = c0 >> 6, d0 = c0 & 63;
                long vb = ((long)(b_ * NH + h0) * HD + d0) * SEQ + sp;
                C[vb] = v0;
                C[vb + SEQ] = v1;
                C[vb + 8] = v2;
                C[vb + SEQ + 8] = v3;
            } else {
                *(float2*)&C[(long)r0 * N + c0] = make_float2(v0, v1);
                *(float2*)&C[(long)(r0 + 8) * N + c0] = make_float2(v2, v3);
            }
        }
    }
}

// ---------------- fused flash attention, q-tile 128, 256 threads (8 warps) ----------
// smem (bytes): Q[128][68] @0, P[128][68] @34816, mask[1024] @69632,
// stages @73728 + s*34816 : K[64][68] then V^T[64][68].  total 143360
#define ATT_SMEM 143360

__global__ __launch_bounds__(256) void attn_kernel(const float* __restrict__ Q,
                                                   const float* __restrict__ Kp,
                                                   const float* __restrict__ Vt,
                                                   const int* __restrict__ mask,
                                                   float* __restrict__ O) {
    extern __shared__ __align__(128) char smc[];
    uint32_t sb = smem_u32(smc);
    float* mAdd = (float*)(smc + 69632);

    int t = threadIdx.x, l = t & 31, warp = t >> 5;
    int g = l >> 2, tg = l & 3;
    int b = blockIdx.z, h = blockIdx.y, qt = blockIdx.x;
    int rq = warp * 16;

    const float* Qb = Q + ((long)(b * SEQ + qt * 128)) * EDIM + h * HD;
    const float* Kb = Kp + ((long)(b * SEQ)) * EDIM + h * HD;
    const float* Vb = Vt + ((long)(b * NH + h) * HD) * SEQ;

    uint32_t aQoff = (uint32_t)((rq + (l & 7) + ((l >> 3) & 1) * 8) * 272 + (l >> 4) * 16);
    uint32_t bOff[4];
#pragma unroll
    for (int j = 0; j < 4; j++)
        bOff[j] = (uint32_t)(((2 * j + (l >> 4)) * 8 + (l & 7)) * 272 + ((l >> 3) & 1) * 16);

    // Q load: 128 rows x 16 segs of 16B, 256 threads
    {
        int r = t >> 1, s0 = (t & 1) * 8;
#pragma unroll
        for (int j = 0; j < 8; j++)
            cp16(sb + (uint32_t)(r * 272 + (s0 + j) * 16), Qb + (long)r * EDIM + (s0 + j) * 4);
        cp_commit();
    }
    for (int i = t; i < SEQ; i += 256) mAdd[i] = mask[b * SEQ + i] ? 0.f : -1e30f;

    // prologue stages 0,1: K/V 64 rows x 16 segs each, 256 threads -> 4 cp16 per tensor
#pragma unroll
    for (int st = 0; st < 2; st++) {
        uint32_t Kst = sb + 73728 + st * 34816, Vst = Kst + 17408;
        int r = t >> 2, j0 = (t & 3) * 4;
        const float* Ks = Kb + (long)(st * 64) * EDIM;
        const float* Vs = Vb + st * 64;
#pragma unroll
        for (int j = 0; j < 4; j++) {
            cp16(Kst + (uint32_t)(r * 272 + (j0 + j) * 16), Ks + (long)r * EDIM + (j0 + j) * 4);
            cp16(Vst + (uint32_t)(r * 272 + (j0 + j) * 16), Vs + (long)r * SEQ + (j0 + j) * 4);
        }
        cp_commit();
    }

    float m_[2] = {-INFINITY, -INFINITY};
    float l_[2] = {0.f, 0.f};
    float o[8][4];
#pragma unroll
    for (int nf = 0; nf < 8; nf++)
#pragma unroll
        for (int q = 0; q < 4; q++) o[nf][q] = 0.f;

    for (int kt = 0; kt < 16; kt++) {
        int s = kt & 1;
        uint32_t Kst = sb + 73728 + s * 34816, Vst = Kst + 17408;
        asm volatile("cp.async.wait_group 1;");
        __syncthreads();

        float sc[8][4];
#pragma unroll
        for (int nf = 0; nf < 8; nf++)
#pragma unroll
            for (int q = 0; q < 4; q++) sc[nf][q] = 0.f;
#pragma unroll
        for (int kk = 0; kk < 8; kk++) {
            uint32_t af[4], bf[8][2];
            ldsm4(af, sb + aQoff + kk * 32);
#pragma unroll
            for (int j = 0; j < 4; j++) ldsm4(&bf[2 * j][0], Kst + bOff[j] + kk * 32);
#pragma unroll
            for (int nf = 0; nf < 8; nf++)
                mma8(sc[nf], af[0], af[1], af[2], af[3], bf[nf][0], bf[nf][1]);
        }

        float rmax0 = -INFINITY, rmax1 = -INFINITY;
#pragma unroll
        for (int nf = 0; nf < 8; nf++) {
            int c0 = kt * 64 + nf * 8 + 2 * tg;
            float ma = mAdd[c0], mb = mAdd[c0 + 1];
            sc[nf][0] = sc[nf][0] * 0.125f + ma;
            sc[nf][1] = sc[nf][1] * 0.125f + mb;
            sc[nf][2] = sc[nf][2] * 0.125f + ma;
            sc[nf][3] = sc[nf][3] * 0.125f + mb;
            rmax0 = fmaxf(rmax0, fmaxf(sc[nf][0], sc[nf][1]));
            rmax1 = fmaxf(rmax1, fmaxf(sc[nf][2], sc[nf][3]));
        }
        rmax0 = fmaxf(rmax0, __shfl_xor_sync(0xffffffffu, rmax0, 1));
        rmax0 = fmaxf(rmax0, __shfl_xor_sync(0xffffffffu, rmax0, 2));
        rmax1 = fmaxf(rmax1, __shfl_xor_sync(0xffffffffu, rmax1, 1));
        rmax1 = fmaxf(rmax1, __shfl_xor_sync(0xffffffffu, rmax1, 2));
        float mn0 = fmaxf(m_[0], rmax0), mn1 = fmaxf(m_[1], rmax1);
        float cf0 = __expf(m_[0] - mn0), cf1 = __expf(m_[1] - mn1);
        float rs0 = 0.f, rs1 = 0.f;
#pragma unroll
        for (int nf = 0; nf < 8; nf++) {
            sc[nf][0] = __expf(sc[nf][0] - mn0);
            sc[nf][1] = __expf(sc[nf][1] - mn0);
            sc[nf][2] = __expf(sc[nf][2] - mn1);
            sc[nf][3] = __expf(sc[nf][3] - mn1);
            rs0 += sc[nf][0] + sc[nf][1];
            rs1 += sc[nf][2] + sc[nf][3];
        }
        rs0 += __shfl_xor_sync(0xffffffffu, rs0, 1);
        rs0 += __shfl_xor_sync(0xffffffffu, rs0, 2);
        rs1 += __shfl_xor_sync(0xffffffffu, rs1, 1);
        rs1 += __shfl_xor_sync(0xffffffffu, rs1, 2);
        l_[0] = l_[0] * cf0 + rs0;
        l_[1] = l_[1] * cf1 + rs1;
        m_[0] = mn0; m_[1] = mn1;
#pragma unroll
        for (int nf = 0; nf < 8; nf++) {
            o[nf][0] *= cf0; o[nf][1] *= cf0;
            o[nf][2] *= cf1; o[nf][3] *= cf1;
        }

#pragma unroll
        for (int nf = 0; nf < 8; nf++) {
            int pc = nf * 8 + 2 * tg;
            uint32_t a0 = sb + 34816 + (uint32_t)((rq + g) * 272 + pc * 4);
            uint32_t a1 = sb + 34816 + (uint32_t)((rq + 8 + g) * 272 + pc * 4);
            asm volatile("st.shared.v2.b32 [%0], {%1, %2};" ::"r"(a0),
                         "r"(f2tf32(sc[nf][0])), "r"(f2tf32(sc[nf][1])) : "memory");
            asm volatile("st.shared.v2.b32 [%0], {%1, %2};" ::"r"(a1),
                         "r"(f2tf32(sc[nf][2])), "r"(f2tf32(sc[nf][3])) : "memory");
        }
        __syncwarp();
#pragma unroll
        for (int kk = 0; kk < 8; kk++) {
            uint32_t af[4], bf[8][2];
            ldsm4(af, sb + 34816 + aQoff + kk * 32);
#pragma unroll
            for (int j = 0; j < 4; j++) ldsm4(&bf[2 * j][0], Vst + bOff[j] + kk * 32);
#pragma unroll
            for (int nf = 0; nf < 8; nf++)
                mma8(o[nf], af[0], af[1], af[2], af[3], bf[nf][0], bf[nf][1]);
        }
        __syncthreads();

        int jn = kt + 2;
        if (jn < 16) {
            int r = t >> 2, j0 = (t & 3) * 4;
            const float* Ks = Kb + (long)(jn * 64) * EDIM;
            const float* Vs = Vb + jn * 64;
#pragma unroll
            for (int j = 0; j < 4; j++) {
                cp16(Kst + (uint32_t)(r * 272 + (j0 + j) * 16), Ks + (long)r * EDIM + (j0 + j) * 4);
                cp16(Vst + (uint32_t)(r * 272 + (j0 + j) * 16), Vs + (long)r * SEQ + (j0 + j) * 4);
            }
        }
        cp_commit();
    }

    float il0 = 1.f / l_[0], il1 = 1.f / l_[1];
#pragma unroll
    for (int nf = 0; nf < 8; nf++) {
        long rowg = (long)(b * SEQ + qt * 128 + rq + g);
        int colg = h * HD + nf * 8 + 2 * tg;
        O[rowg * EDIM + colg] = rna_f(o[nf][0] * il0);
        O[rowg * EDIM + colg + 1] = rna_f(o[nf][1] * il0);
        O[(rowg + 8) * EDIM + colg] = rna_f(o[nf][2] * il1);
        O[(rowg + 8) * EDIM + colg + 1] = rna_f(o[nf][3] * il1);
    }
}

// ---------------- fused residual add + LayerNorm (RNA output) ----------------
__global__ __launch_bounds__(256) void ln_res_kernel(const float* __restrict__ x,
                                                     const float* __restrict__ y,
                                                     const float* __restrict__ gam,
                                                     const float* __restrict__ bet,
                                                     float* __restrict__ out) {
    int row = blockIdx.x, t = threadIdx.x;
    const float* xr = x + (long)row * EDIM;
    const float* yr = y + (long)row * EDIM;
    float v0 = xr[t] + yr[t];
    float v1 = xr[t + 256] + yr[t + 256];
    float v2 = xr[t + 512] + yr[t + 512];
    float s1 = v0 + v1 + v2;
    float s2 = v0 * v0 + v1 * v1 + v2 * v2;
    __shared__ float sh[2][8];
    __shared__ float stats[2];
    int lane = t & 31, w = t >> 5;
#pragma unroll
    for (int off = 16; off; off >>= 1) {
        s1 += __shfl_xor_sync(0xffffffffu, s1, off);
        s2 += __shfl_xor_sync(0xffffffffu, s2, off);
    }
    if (!lane) { sh[0][w] = s1; sh[1][w] = s2; }
    __syncthreads();
    if (t == 0) {
        float a = 0.f, bq = 0.f;
        for (int i = 0; i < 8; i++) { a += sh[0][i]; bq += sh[1][i]; }
        float mean = a * (1.f / EDIM);
        float var = bq * (1.f / EDIM) - mean * mean;
        stats[0] = mean;
        stats[1] = rsqrtf(var + 1e-5f);
    }
    __syncthreads();
    float mean = stats[0], rstd = stats[1];
    long base = (long)row * EDIM;
    out[base + t] = rna_f((v0 - mean) * rstd * gam[t] + bet[t]);
    out[base + t + 256] = rna_f((v1 - mean) * rstd * gam[t + 256] + bet[t + 256]);
    out[base + t + 512] = rna_f((v2 - mean) * rstd * gam[t + 512] + bet[t + 512]);
}

// ---------------- mean pool ----------------
__global__ void pool_kernel(const float* __restrict__ x, float* __restrict__ p) {
    int idx = blockIdx.x * blockDim.x + threadIdx.x;
    if (idx >= 8 * EDIM) return;
    int b = idx / EDIM, e = idx % EDIM;
    const float* xb = x + (long)b * SEQ * EDIM + e;
    float s = 0.f;
    for (int si = 0; si < SEQ; si++) s += xb[(long)si * EDIM];
    p[idx] = s * (1.f / SEQ);
}

// ---------------- classifier ----------------
__global__ void cls_kernel(const float* __restrict__ p, const float* __restrict__ Wc,
                           const float* __restrict__ bc, float* __restrict__ out) {
    int w = threadIdx.x >> 5, lane = threadIdx.x & 31;
    int b = w >> 1, c = w & 1;
    float s = 0.f;
    for (int e = lane; e < EDIM; e += 32) s += p[b * EDIM + e] * Wc[e * 2 + c];
#pragma unroll
    for (int off = 16; off; off >>= 1) s += __shfl_xor_sync(0xffffffffu, s, off);
    if (!lane) out[b * 2 + c] = s + bc[c];
}

// ---------------- launch ----------------
extern "C" void kernel_launch(void* const* d_in, const int* in_sizes, int n_in,
                              void* d_out, int out_size) {
    (void)in_sizes; (void)n_in; (void)out_size;
    const int* ids = (const int*)d_in[0];
    const int* amask = (const int*)d_in[1];
    const float* emb = (const float*)d_in[2];
    const float* pe = (const float*)d_in[3];
    const float* Wq = (const float*)d_in[4];
    const float* bq = (const float*)d_in[5];
    const float* Wk = (const float*)d_in[6];
    const float* bk = (const float*)d_in[7];
    const float* Wv = (const float*)d_in[8];
    const float* bv = (const float*)d_in[9];
    const float* Wo = (const float*)d_in[10];
    const float* bo = (const float*)d_in[11];
    const float* l1g = (const float*)d_in[12];
    const float* l1b = (const float*)d_in[13];
    const float* W1 = (const float*)d_in[14];
    const float* b1 = (const float*)d_in[15];
    const float* W2 = (const float*)d_in[16];
    const float* b2 = (const float*)d_in[17];
    const float* l2g = (const float*)d_in[18];
    const float* l2b = (const float*)d_in[19];
    const float* Wc = (const float*)d_in[20];
    const float* bc = (const float*)d_in[21];
    float* out = (float*)d_out;

    float *x, *q, *k, *v, *att, *tmp, *ffn, *pl, *wt;
    cudaGetSymbolAddress((void**)&x, g_x);
    cudaGetSymbolAddress((void**)&q, g_q);
    cudaGetSymbolAddress((void**)&k, g_k);
    cudaGetSymbolAddress((void**)&v, g_v);
    cudaGetSymbolAddress((void**)&att, g_att);
    cudaGetSymbolAddress((void**)&tmp, g_t);
    cudaGetSymbolAddress((void**)&ffn, g_ffn);
    cudaGetSymbolAddress((void**)&pl, g_pool);
    cudaGetSymbolAddress((void**)&wt, g_wt);

    cudaFuncSetAttribute(gemm_lds, cudaFuncAttributeMaxDynamicSharedMemorySize, GEMM_SMEM);
    cudaFuncSetAttribute(attn_kernel, cudaFuncAttributeMaxDynamicSharedMemorySize, ATT_SMEM);

    // one-time per launch: transpose + RNA-round all weights (batched over layers)
    dim3 tb(32, 8);
    transpose_all<<<dim3(EDIM / 32, EDIM / 32, NLAYER), tb>>>(Wq, wt + 0L * EE, EDIM, EDIM,
                                                             (long)EE, (long)WT_PER_LAYER);
    transpose_all<<<dim3(EDIM / 32, EDIM / 32, NLAYER), tb>>>(Wk, wt + 1L * EE, EDIM, EDIM,
                                                             (long)EE, (long)WT_PER_LAYER);
    transpose_all<<<dim3(EDIM / 32, EDIM / 32, NLAYER), tb>>>(Wv, wt + 2L * EE, EDIM, EDIM,
                                                             (long)EE, (long)WT_PER_LAYER);
    transpose_all<<<dim3(EDIM / 32, EDIM / 32, NLAYER), tb>>>(Wo, wt + 3L * EE, EDIM, EDIM,
                                                             (long)EE, (long)WT_PER_LAYER);
    transpose_all<<<dim3(FDIM / 32, EDIM / 32, NLAYER), tb>>>(W1, wt + 4L * EE, EDIM, FDIM,
                                                             (long)EF, (long)WT_PER_LAYER);
    transpose_all<<<dim3(EDIM / 32, FDIM / 32, NLAYER), tb>>>(W2, wt + 4L * EE + EF, FDIM, EDIM,
                                                             (long)EF, (long)WT_PER_LAYER);

    embed_kernel<<<(TOKS * EDIM + 255) / 256, 256>>>(ids, emb, pe, x);

    for (int l = 0; l < NLAYER; l++) {
        long boff = (long)l * EDIM;
        float* base = wt + (long)l * WT_PER_LAYER;
        Trip tq = {base + 0L * EE, bq + boff, q, 2};
        Trip tk = {base + 1L * EE, bk + boff, k, 2};
        Trip tv = {base + 2L * EE, bv + boff, v, 3};
        gemm_lds<<<dim3(6, 64, 3), 256, GEMM_SMEM>>>(x, tq, tk, tv, EDIM, EDIM);
        attn_kernel<<<dim3(8, 12, 8), 256, ATT_SMEM>>>(q, k, v, amask, att);
        Trip to = {base + 3L * EE, bo + boff, tmp, 0};
        gemm_lds<<<dim3(6, 64, 1), 256, GEMM_SMEM>>>(att, to, to, to, EDIM, EDIM);
        ln_res_kernel<<<TOKS, 256>>>(x, tmp, l1g + boff, l1b + boff, x);
        Trip t1 = {base + 4L * EE, b1 + (long)l * FDIM, ffn, 1};
        gemm_lds<<<dim3(24, 64, 1), 256, GEMM_SMEM>>>(x, t1, t1, t1, FDIM, EDIM);
        Trip t2 = {base + 4L * EE + EF, b2 + boff, tmp, 0};
        gemm_lds<<<dim3(6, 64, 1), 256, GEMM_SMEM>>>(ffn, t2, t2, t2, EDIM, FDIM);
        ln_res_kernel<<<TOKS, 256>>>(x, tmp, l2g + boff, l2b + boff, x);
    }

    pool_kernel<<<(8 * EDIM + 255) / 256, 256>>>(x, pl);
    cls_kernel<<<1, 512>>>(pl, Wc, bc, out);
}